// round 7
// baseline (speedup 1.0000x reference)
#include <cuda_runtime.h>
#include <cstdint>

// ---------------------------------------------------------------------------
// Problem constants
// ---------------------------------------------------------------------------
#define BSZ  2
#define HN   12
#define TN   2048
#define DH   64
#define DIMN 768

#define QTIL 128   // q rows per block (8 warps x 16 rows)
#define KTIL 64    // keys per main-loop iteration

__device__ float g_y[BSZ * TN * DIMN];  // intermediate (B, T, H*D)

// ---------------------------------------------------------------------------
// bf16 split helpers (bit tricks; round-to-nearest via +0x8000)
// ---------------------------------------------------------------------------
__device__ __forceinline__ uint32_t bfhi(float x) {
    return (__float_as_uint(x) + 0x8000u) & 0xFFFF0000u;
}
__device__ __forceinline__ void split2(float x0, float x1, uint32_t& hp, uint32_t& lp) {
    uint32_t h0 = bfhi(x0), h1 = bfhi(x1);
    float l0 = x0 - __uint_as_float(h0);
    float l1 = x1 - __uint_as_float(h1);
    hp = (h0 >> 16) | h1;
    lp = (bfhi(l0) >> 16) | bfhi(l1);
}
// old-style swizzle (still used by proj kernel)
__device__ __forceinline__ int fsw(int r) {
    return ((r & 7) << 2) ^ ((r >> 3) & 3);
}

__device__ __forceinline__ void mma16816(float* c,
    uint32_t a0, uint32_t a1, uint32_t a2, uint32_t a3, uint32_t b0, uint32_t b1) {
    asm volatile(
        "mma.sync.aligned.m16n8k16.row.col.f32.bf16.bf16.f32 "
        "{%0,%1,%2,%3}, {%4,%5,%6,%7}, {%8,%9}, {%0,%1,%2,%3};"
        : "+f"(c[0]), "+f"(c[1]), "+f"(c[2]), "+f"(c[3])
        : "r"(a0), "r"(a1), "r"(a2), "r"(a3), "r"(b0), "r"(b1));
}

__device__ __forceinline__ uint32_t smem_u32(const void* p) {
    uint32_t a;
    asm("{ .reg .u64 t; cvta.to.shared.u64 t, %1; cvt.u32.u64 %0, t; }" : "=r"(a) : "l"(p));
    return a;
}
__device__ __forceinline__ void cpasync16(uint32_t dst, const void* src) {
    asm volatile("cp.async.cg.shared.global [%0], [%1], 16;" :: "r"(dst), "l"(src));
}
#define CP_COMMIT() asm volatile("cp.async.commit_group;" ::: "memory")
#define CP_WAIT0()  asm volatile("cp.async.wait_group 0;" ::: "memory")

__device__ __forceinline__ void ldsm4(uint32_t* r, uint32_t a) {
    asm volatile("ldmatrix.sync.aligned.m8n8.x4.shared.b16 {%0,%1,%2,%3}, [%4];"
        : "=r"(r[0]), "=r"(r[1]), "=r"(r[2]), "=r"(r[3]) : "r"(a));
}

// ---------------------------------------------------------------------------
// Flash attention, bf16 mma.sync 3-pass, cp.async pipeline + ldmatrix frags.
// Block: 256 threads (8 warps, 16 q-rows each). Grid: (16, B*H).
// Dynamic smem 64KB (u32 words). Tile rows = 32 words (64 bf16), 8 chunks of
// 16B; chunk-granular swizzle: word' = word ^ ((row&7)<<2).
//   [0    .. 2047]  Kh  | Q hi rows 0..63 (prologue)
//   [2048 .. 4095]  Kl  | Q hi rows 64..127
//   [4096 .. 6143]  Vth | Q lo rows 0..63
//   [6144 .. 8191]  Vtl | Q lo rows 64..127
//   [8192 ..12287]  raw K tile (64x64 f32)
//   [12288..16383]  raw V tile (64x64 f32)
// ---------------------------------------------------------------------------
#define RAWK 8192
#define RAWV 12288
#define ATTN_SMEM (16384 * 4)

__global__ __launch_bounds__(256) void attn_mma_kernel(
    const float* __restrict__ q, const float* __restrict__ k,
    const float* __restrict__ v, const float* __restrict__ bias)
{
    extern __shared__ uint32_t pool[];

    const int tid  = threadIdx.x;
    const int wid  = tid >> 5;
    const int lane = tid & 31;
    const int gr   = lane >> 2;
    const int tc   = lane & 3;
    const int qt   = gridDim.x - 1 - blockIdx.x;   // big tiles first
    const int bh   = blockIdx.y;
    const int q0   = qt * QTIL;
    const int r0   = wid * 16 + gr;
    const int row_g0 = q0 + r0;
    const int row_g1 = row_g0 + 8;

    // ldmatrix per-lane constants (B-frag x4 loads: 4 groups of 8 lanes)
    const int l8   = lane & 7;
    const int rsel = (lane & 16) ? 8 : 0;   // groups 2,3 -> rows +8
    const int cpar = (lane >> 3) & 1;       // groups 1,3 -> odd chunk
    const uint32_t base_b  = smem_u32(pool);
    const uint32_t krow_b  = base_b + (uint32_t)(rsel + l8) * 128;

    const uint32_t rawk_b = smem_u32(pool + RAWK);
    const uint32_t rawv_b = smem_u32(pool + RAWV);
    const float* kbase = k + (size_t)bh * TN * DH;
    const float* vbase = v + (size_t)bh * TN * DH;

    // ---- prologue: kick off cp.async for tile 0 ----
    {
#pragma unroll
        for (int i = 0; i < 4; ++i) {
            int idx = tid + i * 256;
            cpasync16(rawk_b + idx * 16, kbase + idx * 4);
            cpasync16(rawv_b + idx * 16, vbase + idx * 4);
        }
        CP_COMMIT();
    }

    // ---- stage Q (hi/lo) into pool (chunk-swizzled), then ldmatrix frags ----
    {
        const float* qp = q + ((size_t)bh * TN + q0) * DH;
#pragma unroll
        for (int i = 0; i < 8; ++i) {
            int idx = tid + i * 256;
            int r = idx >> 4, c = idx & 15;
            float4 x = reinterpret_cast<const float4*>(qp + (size_t)r * DH)[c];
            uint32_t h0, l0, h1, l1;
            split2(x.x, x.y, h0, l0);
            split2(x.z, x.w, h1, l1);
            int wof = (2 * c) ^ ((r & 7) << 2);
            uint2 hv; hv.x = h0; hv.y = h1;
            uint2 lv; lv.x = l0; lv.y = l1;
            *reinterpret_cast<uint2*>(&pool[r * 32 + wof])        = hv;
            *reinterpret_cast<uint2*>(&pool[4096 + r * 32 + wof]) = lv;
        }
    }
    __syncthreads();

    uint32_t qh[4][4], ql[4][4];
    {
        const uint32_t qrow = base_b + (uint32_t)(wid * 16 + (lane & 15)) * 128;
#pragma unroll
        for (int s = 0; s < 4; ++s) {
            int chunk = 2 * s + (lane >> 4);
            uint32_t sw = (uint32_t)((chunk ^ (lane & 7)) << 4);
            ldsm4(qh[s], qrow + sw);
            ldsm4(ql[s], qrow + 16384 + sw);
        }
    }

    float O[8][4];
#pragma unroll
    for (int n = 0; n < 8; ++n)
#pragma unroll
        for (int i = 0; i < 4; ++i) O[n][i] = 0.f;
    float m0 = -1e30f, m1 = -1e30f, l0 = 0.f, l1 = 0.f;

    const float* b0p = bias + ((size_t)bh * TN + row_g0) * TN;
    const float* b1p = b0p + (size_t)8 * TN;

    const int nj = 2 * qt + 2;
    for (int j = 0; j < nj; ++j) {
        const int kv0 = j * KTIL;

        // ---- wait raw tile j; frags of tile j-1 fully consumed ----
        CP_WAIT0();
        __syncthreads();

        // ---- split raw K -> Kh/Kl (chunk-swizzled, uint2 stores) ----
        {
            const float4* kraw = reinterpret_cast<const float4*>(pool + RAWK);
#pragma unroll
            for (int i = 0; i < 4; ++i) {
                int idx = tid + i * 256;
                int r = idx >> 4, c = idx & 15;
                float4 x = kraw[idx];
                uint32_t h0, lo0, h1, lo1;
                split2(x.x, x.y, h0, lo0);
                split2(x.z, x.w, h1, lo1);
                int wof = (2 * c) ^ ((r & 7) << 2);
                uint2 hv; hv.x = h0; hv.y = h1;
                uint2 lv; lv.x = lo0; lv.y = lo1;
                *reinterpret_cast<uint2*>(&pool[r * 32 + wof])        = hv;
                *reinterpret_cast<uint2*>(&pool[2048 + r * 32 + wof]) = lv;
            }
        }
        // ---- split raw V (transposed) -> Vth/Vtl (uint4 stores) ----
        {
            const float* vraw = reinterpret_cast<const float*>(pool + RAWV);
            const int d = tid & 63;
#pragma unroll
            for (int o2 = 0; o2 < 2; ++o2) {
                int o = (tid >> 6) + 4 * o2;
                float vv[8];
#pragma unroll
                for (int jj = 0; jj < 8; ++jj)
                    vv[jj] = vraw[(8 * o + jj) * 64 + d];
                uint32_t hw[4], lw[4];
#pragma unroll
                for (int p2 = 0; p2 < 4; ++p2)
                    split2(vv[2 * p2], vv[2 * p2 + 1], hw[p2], lw[p2]);
                int wof = (4 * o) ^ ((d & 7) << 2);
                uint4 hv; hv.x = hw[0]; hv.y = hw[1]; hv.z = hw[2]; hv.w = hw[3];
                uint4 lv; lv.x = lw[0]; lv.y = lw[1]; lv.z = lw[2]; lv.w = lw[3];
                *reinterpret_cast<uint4*>(&pool[4096 + d * 32 + wof]) = hv;
                *reinterpret_cast<uint4*>(&pool[6144 + d * 32 + wof]) = lv;
            }
        }
        __syncthreads();   // splits visible; raw fully consumed

        // ---- kick off cp.async for tile j+1 (lands during mma) ----
        if (j + 1 < nj) {
            const float* kp = kbase + (size_t)(kv0 + KTIL) * DH;
            const float* vp = vbase + (size_t)(kv0 + KTIL) * DH;
#pragma unroll
            for (int i = 0; i < 4; ++i) {
                int idx = tid + i * 256;
                cpasync16(rawk_b + idx * 16, kp + idx * 4);
                cpasync16(rawv_b + idx * 16, vp + idx * 4);
            }
            CP_COMMIT();
        }

        // ---- prefetch bias into registers (consumed after QK mmas) ----
        float2 bb0r[8], bb1r[8];
#pragma unroll
        for (int n = 0; n < 8; ++n) {
            int col = kv0 + 8 * n + 2 * tc;
            bb0r[n] = *reinterpret_cast<const float2*>(b0p + col);
            bb1r[n] = *reinterpret_cast<const float2*>(b1p + col);
        }

        // ---- S = Q K^T (3-pass bf16, ldmatrix B-frags) ----
        float S[8][4];
#pragma unroll
        for (int n = 0; n < 8; ++n)
#pragma unroll
            for (int i = 0; i < 4; ++i) S[n][i] = 0.f;

#pragma unroll
        for (int s = 0; s < 4; ++s) {
            uint32_t sw = (uint32_t)((((2 * s + cpar) ^ l8)) << 4);
#pragma unroll
            for (int np = 0; np < 4; ++np) {
                uint32_t kh4[4], kl4[4];
                uint32_t a = krow_b + np * 2048 + sw;
                ldsm4(kh4, a);
                ldsm4(kl4, a + 8192);
                float* S0 = S[2 * np];
                float* S1 = S[2 * np + 1];
                mma16816(S0, qh[s][0], qh[s][1], qh[s][2], qh[s][3], kh4[0], kh4[1]);
                mma16816(S0, qh[s][0], qh[s][1], qh[s][2], qh[s][3], kl4[0], kl4[1]);
                mma16816(S0, ql[s][0], ql[s][1], ql[s][2], ql[s][3], kh4[0], kh4[1]);
                mma16816(S1, qh[s][0], qh[s][1], qh[s][2], qh[s][3], kh4[2], kh4[3]);
                mma16816(S1, qh[s][0], qh[s][1], qh[s][2], qh[s][3], kl4[2], kl4[3]);
                mma16816(S1, ql[s][0], ql[s][1], ql[s][2], ql[s][3], kh4[2], kh4[3]);
            }
        }

        // ---- scale + bias + causal mask ----
        const bool domask = (j >= 2 * qt);
#pragma unroll
        for (int n = 0; n < 8; ++n) {
            int col = kv0 + 8 * n + 2 * tc;
            S[n][0] = fmaf(S[n][0], 0.125f, bb0r[n].x);
            S[n][1] = fmaf(S[n][1], 0.125f, bb0r[n].y);
            S[n][2] = fmaf(S[n][2], 0.125f, bb1r[n].x);
            S[n][3] = fmaf(S[n][3], 0.125f, bb1r[n].y);
            if (domask) {
                if (col     > row_g0) S[n][0] = -1e30f;
                if (col + 1 > row_g0) S[n][1] = -1e30f;
                if (col     > row_g1) S[n][2] = -1e30f;
                if (col + 1 > row_g1) S[n][3] = -1e30f;
            }
        }

        // ---- online softmax ----
        float t0 = -1e30f, t1 = -1e30f;
#pragma unroll
        for (int n = 0; n < 8; ++n) {
            t0 = fmaxf(t0, fmaxf(S[n][0], S[n][1]));
            t1 = fmaxf(t1, fmaxf(S[n][2], S[n][3]));
        }
        t0 = fmaxf(t0, __shfl_xor_sync(0xffffffffu, t0, 1));
        t0 = fmaxf(t0, __shfl_xor_sync(0xffffffffu, t0, 2));
        t1 = fmaxf(t1, __shfl_xor_sync(0xffffffffu, t1, 1));
        t1 = fmaxf(t1, __shfl_xor_sync(0xffffffffu, t1, 2));
        float mn0 = fmaxf(m0, t0), mn1 = fmaxf(m1, t1);
        float c0 = __expf(m0 - mn0), c1 = __expf(m1 - mn1);
        m0 = mn0; m1 = mn1;
        float ls0 = 0.f, ls1 = 0.f;
#pragma unroll
        for (int n = 0; n < 8; ++n) {
            S[n][0] = __expf(S[n][0] - m0); ls0 += S[n][0];
            S[n][1] = __expf(S[n][1] - m0); ls0 += S[n][1];
            S[n][2] = __expf(S[n][2] - m1); ls1 += S[n][2];
            S[n][3] = __expf(S[n][3] - m1); ls1 += S[n][3];
        }
        l0 = l0 * c0 + ls0;
        l1 = l1 * c1 + ls1;
#pragma unroll
        for (int n = 0; n < 8; ++n) {
            O[n][0] *= c0; O[n][1] *= c0;
            O[n][2] *= c1; O[n][3] *= c1;
        }

        // ---- O += P V (3-pass bf16); P C-frag -> A-frag in registers ----
#pragma unroll
        for (int s = 0; s < 4; ++s) {
            uint32_t ph0, ph1, ph2, ph3, pl0, pl1, pl2, pl3;
            split2(S[2 * s][0],     S[2 * s][1],     ph0, pl0);
            split2(S[2 * s][2],     S[2 * s][3],     ph1, pl1);
            split2(S[2 * s + 1][0], S[2 * s + 1][1], ph2, pl2);
            split2(S[2 * s + 1][2], S[2 * s + 1][3], ph3, pl3);
            uint32_t sw = (uint32_t)((((2 * s + cpar) ^ l8)) << 4);
#pragma unroll
            for (int np = 0; np < 4; ++np) {
                uint32_t vh4[4], vl4[4];
                uint32_t a = krow_b + 16384 + np * 2048 + sw;
                ldsm4(vh4, a);
                ldsm4(vl4, a + 8192);
                float* O0 = O[2 * np];
                float* O1 = O[2 * np + 1];
                mma16816(O0, ph0, ph1, ph2, ph3, vh4[0], vh4[1]);
                mma16816(O0, ph0, ph1, ph2, ph3, vl4[0], vl4[1]);
                mma16816(O0, pl0, pl1, pl2, pl3, vh4[0], vh4[1]);
                mma16816(O1, ph0, ph1, ph2, ph3, vh4[2], vh4[3]);
                mma16816(O1, ph0, ph1, ph2, ph3, vl4[2], vl4[3]);
                mma16816(O1, pl0, pl1, pl2, pl3, vh4[2], vh4[3]);
            }
        }
        __syncthreads();   // PV reads done before next split overwrites pool
    }

    // ---- finalize: O / l -> g_y (B, T, H*D) ----
    l0 += __shfl_xor_sync(0xffffffffu, l0, 1);
    l0 += __shfl_xor_sync(0xffffffffu, l0, 2);
    l1 += __shfl_xor_sync(0xffffffffu, l1, 1);
    l1 += __shfl_xor_sync(0xffffffffu, l1, 2);
    float inv0 = 1.f / l0, inv1 = 1.f / l1;

    const int b = bh / HN, h = bh % HN;
    float* o0 = g_y + ((size_t)b * TN + row_g0) * DIMN + h * DH;
    float* o1 = g_y + ((size_t)b * TN + row_g1) * DIMN + h * DH;
#pragma unroll
    for (int n = 0; n < 8; ++n) {
        int col = 8 * n + 2 * tc;
        float2 w0, w1;
        w0.x = O[n][0] * inv0; w0.y = O[n][1] * inv0;
        w1.x = O[n][2] * inv1; w1.y = O[n][3] * inv1;
        *reinterpret_cast<float2*>(o0 + col) = w0;
        *reinterpret_cast<float2*>(o1 + col) = w1;
    }
}

// ---------------------------------------------------------------------------
// Projection GEMM via mma.sync bf16 3-pass (unchanged from round 5/6)
// ---------------------------------------------------------------------------
__global__ __launch_bounds__(256) void proj_mma_kernel(
    const float* __restrict__ W, float* __restrict__ out)
{
    extern __shared__ uint32_t pp[];

    const int tid  = threadIdx.x;
    const int wid  = tid >> 5;
    const int lane = tid & 31;
    const int gr   = lane >> 2;
    const int tc   = lane & 3;
    const int m_blk = blockIdx.y * 128;
    const int n_blk = blockIdx.x * 128;
    const int wm = (wid >> 1) * 32;
    const int wn = (wid & 1) * 64;

    float C[2][8][4];
#pragma unroll
    for (int mi = 0; mi < 2; ++mi)
#pragma unroll
        for (int n = 0; n < 8; ++n)
#pragma unroll
            for (int i = 0; i < 4; ++i) C[mi][n][i] = 0.f;

    for (int k0 = 0; k0 < DIMN; k0 += 64) {
        {
            const float* ap = g_y + (size_t)m_blk * DIMN + k0;
#pragma unroll
            for (int i = 0; i < 8; ++i) {
                int idx = tid + i * 256;
                int r = idx >> 4, c = idx & 15;
                float4 x = reinterpret_cast<const float4*>(ap + (size_t)r * DIMN)[c];
                uint32_t h0, l0, h1, l1;
                split2(x.x, x.y, h0, l0);
                split2(x.z, x.w, h1, l1);
                int s = fsw(r);
                pp[r * 32 + ((2 * c) ^ s)]            = h0;
                pp[r * 32 + ((2 * c + 1) ^ s)]        = h1;
                pp[4096 + r * 32 + ((2 * c) ^ s)]     = l0;
                pp[4096 + r * 32 + ((2 * c + 1) ^ s)] = l1;
            }
        }
        {
            const int d = tid & 127;
            const int hf = tid >> 7;
            const int s = fsw(d);
            const float* wp = W + (size_t)k0 * DIMN + n_blk + d;
#pragma unroll
            for (int oo = 0; oo < 4; ++oo) {
                int o = hf + 2 * oo;
                float w8[8];
#pragma unroll
                for (int jj = 0; jj < 8; ++jj)
                    w8[jj] = wp[(size_t)(8 * o + jj) * DIMN];
#pragma unroll
                for (int p2 = 0; p2 < 4; ++p2) {
                    uint32_t hp, lp;
                    split2(w8[2 * p2], w8[2 * p2 + 1], hp, lp);
                    pp[8192  + d * 32 + ((4 * o + p2) ^ s)] = hp;
                    pp[12288 + d * 32 + ((4 * o + p2) ^ s)] = lp;
                }
            }
        }
        __syncthreads();

#pragma unroll
        for (int s = 0; s < 4; ++s) {
            const int w0 = tc + 8 * s, w1 = w0 + 4;
            uint32_t ah[2][4], al[2][4];
#pragma unroll
            for (int mi = 0; mi < 2; ++mi) {
                int ra = wm + 16 * mi + gr, rb = ra + 8;
                int sa = fsw(ra), sb = fsw(rb);
                ah[mi][0] = pp[ra * 32 + (w0 ^ sa)];
                ah[mi][1] = pp[rb * 32 + (w0 ^ sb)];
                ah[mi][2] = pp[ra * 32 + (w1 ^ sa)];
                ah[mi][3] = pp[rb * 32 + (w1 ^ sb)];
                al[mi][0] = pp[4096 + ra * 32 + (w0 ^ sa)];
                al[mi][1] = pp[4096 + rb * 32 + (w0 ^ sb)];
                al[mi][2] = pp[4096 + ra * 32 + (w1 ^ sa)];
                al[mi][3] = pp[4096 + rb * 32 + (w1 ^ sb)];
            }
#pragma unroll
            for (int n = 0; n < 8; ++n) {
                int br = wn + 8 * n + gr;
                int sw = fsw(br);
                uint32_t bh0 = pp[8192  + br * 32 + (w0 ^ sw)];
                uint32_t bh1 = pp[8192  + br * 32 + (w1 ^ sw)];
                uint32_t bl0 = pp[12288 + br * 32 + (w0 ^ sw)];
                uint32_t bl1 = pp[12288 + br * 32 + (w1 ^ sw)];
#pragma unroll
                for (int mi = 0; mi < 2; ++mi) {
                    mma16816(C[mi][n], ah[mi][0], ah[mi][1], ah[mi][2], ah[mi][3], bh0, bh1);
                    mma16816(C[mi][n], ah[mi][0], ah[mi][1], ah[mi][2], ah[mi][3], bl0, bl1);
                    mma16816(C[mi][n], al[mi][0], al[mi][1], al[mi][2], al[mi][3], bh0, bh1);
                }
            }
        }
        __syncthreads();
    }

#pragma unroll
    for (int mi = 0; mi < 2; ++mi) {
        int row0 = m_blk + wm + 16 * mi + gr;
        int row1 = row0 + 8;
#pragma unroll
        for (int n = 0; n < 8; ++n) {
            int col = n_blk + wn + 8 * n + 2 * tc;
            float2 w0, w1;
            w0.x = C[mi][n][0]; w0.y = C[mi][n][1];
            w1.x = C[mi][n][2]; w1.y = C[mi][n][3];
            *reinterpret_cast<float2*>(out + (size_t)row0 * DIMN + col) = w0;
            *reinterpret_cast<float2*>(out + (size_t)row1 * DIMN + col) = w1;
        }
    }
}

extern "C" void kernel_launch(void* const* d_in, const int* in_sizes, int n_in,
                              void* d_out, int out_size)
{
    (void)in_sizes; (void)n_in; (void)out_size;
    const float* q    = (const float*)d_in[0];
    const float* k    = (const float*)d_in[1];
    const float* v    = (const float*)d_in[2];
    const float* bias = (const float*)d_in[3];
    const float* W    = (const float*)d_in[4];
    float* out = (float*)d_out;

    cudaFuncSetAttribute(attn_mma_kernel,
                         cudaFuncAttributeMaxDynamicSharedMemorySize, ATTN_SMEM);
    attn_mma_kernel<<<dim3(TN / QTIL, BSZ * HN), 256, ATTN_SMEM>>>(q, k, v, bias);

    const int PROJ_SMEM = 16384 * 4;   // 64KB
    cudaFuncSetAttribute(proj_mma_kernel,
                         cudaFuncAttributeMaxDynamicSharedMemorySize, PROJ_SMEM);
    proj_mma_kernel<<<dim3(DIMN / 128, (BSZ * TN) / 128), 256, PROJ_SMEM>>>(W, out);
}

// round 10
// speedup vs baseline: 1.1233x; 1.1233x over previous
#include <cuda_runtime.h>
#include <cstdint>

// ---------------------------------------------------------------------------
// Problem constants
// ---------------------------------------------------------------------------
#define BSZ  2
#define HN   12
#define TN   2048
#define DH   64
#define DIMN 768

#define QTIL 128   // q rows per block (8 warps x 16 rows)
#define KTIL 64    // keys per main-loop iteration

// Pre-split intermediates (packed bf16 pairs: word = [k even | k odd])
__device__ uint32_t g_yh[BSZ * TN * (DIMN / 2)];
__device__ uint32_t g_yl[BSZ * TN * (DIMN / 2)];
__device__ uint32_t g_wth[DIMN * (DIMN / 2)];   // W^T hi: [n][k pairs]
__device__ uint32_t g_wtl[DIMN * (DIMN / 2)];   // W^T lo

// ---------------------------------------------------------------------------
// bf16 split helpers
// ---------------------------------------------------------------------------
__device__ __forceinline__ uint32_t bfhi(float x) {
    return (__float_as_uint(x) + 0x8000u) & 0xFFFF0000u;
}
__device__ __forceinline__ void split2(float x0, float x1, uint32_t& hp, uint32_t& lp) {
    uint32_t h0 = bfhi(x0), h1 = bfhi(x1);
    float l0 = x0 - __uint_as_float(h0);
    float l1 = x1 - __uint_as_float(h1);
    hp = (h0 >> 16) | h1;
    lp = (bfhi(l0) >> 16) | bfhi(l1);
}
// word-level swizzle used by the attention kernel (R6 proven layout)
__device__ __forceinline__ int fsw(int r) {
    return ((r & 7) << 2) ^ ((r >> 3) & 3);
}

__device__ __forceinline__ void mma16816(float* c,
    uint32_t a0, uint32_t a1, uint32_t a2, uint32_t a3, uint32_t b0, uint32_t b1) {
    asm volatile(
        "mma.sync.aligned.m16n8k16.row.col.f32.bf16.bf16.f32 "
        "{%0,%1,%2,%3}, {%4,%5,%6,%7}, {%8,%9}, {%0,%1,%2,%3};"
        : "+f"(c[0]), "+f"(c[1]), "+f"(c[2]), "+f"(c[3])
        : "r"(a0), "r"(a1), "r"(a2), "r"(a3), "r"(b0), "r"(b1));
}

__device__ __forceinline__ uint32_t smem_u32(const void* p) {
    uint32_t a;
    asm("{ .reg .u64 t; cvta.to.shared.u64 t, %1; cvt.u32.u64 %0, t; }" : "=r"(a) : "l"(p));
    return a;
}
__device__ __forceinline__ void cpasync16(uint32_t dst, const void* src) {
    asm volatile("cp.async.cg.shared.global [%0], [%1], 16;" :: "r"(dst), "l"(src));
}
#define CP_COMMIT() asm volatile("cp.async.commit_group;" ::: "memory")
#define CP_WAIT0()  asm volatile("cp.async.wait_group 0;" ::: "memory")
#define CP_WAIT1()  asm volatile("cp.async.wait_group 1;" ::: "memory")

__device__ __forceinline__ void ldsm4(uint32_t* r, uint32_t a) {
    asm volatile("ldmatrix.sync.aligned.m8n8.x4.shared.b16 {%0,%1,%2,%3}, [%4];"
        : "=r"(r[0]), "=r"(r[1]), "=r"(r[2]), "=r"(r[3]) : "r"(a));
}

// ---------------------------------------------------------------------------
// Prep: W (k-major fp32) -> W^T hi/lo (n-major packed bf16 pairs).
// Grid (12, 12), 256 threads, 64x64 tiles via smem transpose.
// ---------------------------------------------------------------------------
__global__ __launch_bounds__(256) void prep_w_kernel(const float* __restrict__ W)
{
    __shared__ float t[64][65];
    const int tid = threadIdx.x;
    const int n0 = blockIdx.x * 64, k0 = blockIdx.y * 64;
#pragma unroll
    for (int i = 0; i < 16; ++i) {
        int idx = tid + i * 256;
        int r = idx >> 6, c = idx & 63;
        t[r][c] = W[(size_t)(k0 + r) * DIMN + n0 + c];
    }
    __syncthreads();
#pragma unroll
    for (int i = 0; i < 8; ++i) {
        int idx = tid + i * 256;
        int c = idx >> 5, j = idx & 31;       // n-col c, k-pair j
        uint32_t hp, lp;
        split2(t[2 * j][c], t[2 * j + 1][c], hp, lp);
        size_t o = (size_t)(n0 + c) * (DIMN / 2) + (k0 >> 1) + j;
        g_wth[o] = hp;
        g_wtl[o] = lp;
    }
}

// ---------------------------------------------------------------------------
// Flash attention (R6 best: cp.async pipeline, fsw swizzle, scalar frag LDS).
// Only change vs R6: epilogue writes packed bf16 hi/lo y instead of fp32.
// ---------------------------------------------------------------------------
#define RAWK 8192
#define RAWV 12288
#define ATTN_SMEM (16384 * 4)

__global__ __launch_bounds__(256) void attn_mma_kernel(
    const float* __restrict__ q, const float* __restrict__ k,
    const float* __restrict__ v, const float* __restrict__ bias)
{
    extern __shared__ uint32_t pool[];

    const int tid  = threadIdx.x;
    const int wid  = tid >> 5;
    const int lane = tid & 31;
    const int gr   = lane >> 2;
    const int tc   = lane & 3;
    const int qt   = gridDim.x - 1 - blockIdx.x;
    const int bh   = blockIdx.y;
    const int q0   = qt * QTIL;
    const int r0   = wid * 16 + gr;
    const int row_g0 = q0 + r0;
    const int row_g1 = row_g0 + 8;

    const uint32_t rawk_b = smem_u32(pool + RAWK);
    const uint32_t rawv_b = smem_u32(pool + RAWV);
    const float* kbase = k + (size_t)bh * TN * DH;
    const float* vbase = v + (size_t)bh * TN * DH;

    {
#pragma unroll
        for (int i = 0; i < 4; ++i) {
            int idx = tid + i * 256;
            cpasync16(rawk_b + idx * 16, kbase + idx * 4);
            cpasync16(rawv_b + idx * 16, vbase + idx * 4);
        }
        CP_COMMIT();
    }

    {
        const float* qp = q + ((size_t)bh * TN + q0) * DH;
#pragma unroll
        for (int i = 0; i < 8; ++i) {
            int idx = tid + i * 256;
            int r = idx >> 4, c = idx & 15;
            float4 x = reinterpret_cast<const float4*>(qp + (size_t)r * DH)[c];
            uint32_t h0, l0, h1, l1;
            split2(x.x, x.y, h0, l0);
            split2(x.z, x.w, h1, l1);
            int s = fsw(r);
            pool[r * 32 + ((2 * c) ^ s)]            = h0;
            pool[r * 32 + ((2 * c + 1) ^ s)]        = h1;
            pool[4096 + r * 32 + ((2 * c) ^ s)]     = l0;
            pool[4096 + r * 32 + ((2 * c + 1) ^ s)] = l1;
        }
    }
    __syncthreads();

    uint32_t qh[4][4], ql[4][4];
    {
        const int ra = r0, rb = r0 + 8;
        const int sa = fsw(ra), sb = fsw(rb);
#pragma unroll
        for (int s = 0; s < 4; ++s) {
            int w0 = tc + 8 * s, w1 = w0 + 4;
            qh[s][0] = pool[ra * 32 + (w0 ^ sa)];
            qh[s][1] = pool[rb * 32 + (w0 ^ sb)];
            qh[s][2] = pool[ra * 32 + (w1 ^ sa)];
            qh[s][3] = pool[rb * 32 + (w1 ^ sb)];
            ql[s][0] = pool[4096 + ra * 32 + (w0 ^ sa)];
            ql[s][1] = pool[4096 + rb * 32 + (w0 ^ sb)];
            ql[s][2] = pool[4096 + ra * 32 + (w1 ^ sa)];
            ql[s][3] = pool[4096 + rb * 32 + (w1 ^ sb)];
        }
    }

    float O[8][4];
#pragma unroll
    for (int n = 0; n < 8; ++n)
#pragma unroll
        for (int i = 0; i < 4; ++i) O[n][i] = 0.f;
    float m0 = -1e30f, m1 = -1e30f, l0 = 0.f, l1 = 0.f;

    const float* b0p = bias + ((size_t)bh * TN + row_g0) * TN;
    const float* b1p = b0p + (size_t)8 * TN;

    const int nj = 2 * qt + 2;
    for (int j = 0; j < nj; ++j) {
        const int kv0 = j * KTIL;

        CP_WAIT0();
        __syncthreads();

        {
            const float4* kraw = reinterpret_cast<const float4*>(pool + RAWK);
#pragma unroll
            for (int i = 0; i < 4; ++i) {
                int idx = tid + i * 256;
                int r = idx >> 4, c = idx & 15;
                float4 x = kraw[idx];
                uint32_t h0, lo0, h1, lo1;
                split2(x.x, x.y, h0, lo0);
                split2(x.z, x.w, h1, lo1);
                int s = fsw(r);
                pool[r * 32 + ((2 * c) ^ s)]            = h0;
                pool[r * 32 + ((2 * c + 1) ^ s)]        = h1;
                pool[2048 + r * 32 + ((2 * c) ^ s)]     = lo0;
                pool[2048 + r * 32 + ((2 * c + 1) ^ s)] = lo1;
            }
        }
        {
            const float* vraw = reinterpret_cast<const float*>(pool + RAWV);
            const int d = tid & 63;
            const int s = fsw(d);
#pragma unroll
            for (int o2 = 0; o2 < 2; ++o2) {
                int o = (tid >> 6) + 4 * o2;
                float vv[8];
#pragma unroll
                for (int jj = 0; jj < 8; ++jj)
                    vv[jj] = vraw[(8 * o + jj) * 64 + d];
#pragma unroll
                for (int p2 = 0; p2 < 4; ++p2) {
                    uint32_t hp, lp;
                    split2(vv[2 * p2], vv[2 * p2 + 1], hp, lp);
                    pool[4096 + d * 32 + ((4 * o + p2) ^ s)] = hp;
                    pool[6144 + d * 32 + ((4 * o + p2) ^ s)] = lp;
                }
            }
        }
        __syncthreads();

        if (j + 1 < nj) {
            const float* kp = kbase + (size_t)(kv0 + KTIL) * DH;
            const float* vp = vbase + (size_t)(kv0 + KTIL) * DH;
#pragma unroll
            for (int i = 0; i < 4; ++i) {
                int idx = tid + i * 256;
                cpasync16(rawk_b + idx * 16, kp + idx * 4);
                cpasync16(rawv_b + idx * 16, vp + idx * 4);
            }
            CP_COMMIT();
        }

        float2 bb0r[8], bb1r[8];
#pragma unroll
        for (int n = 0; n < 8; ++n) {
            int col = kv0 + 8 * n + 2 * tc;
            bb0r[n] = *reinterpret_cast<const float2*>(b0p + col);
            bb1r[n] = *reinterpret_cast<const float2*>(b1p + col);
        }

        float S[8][4];
#pragma unroll
        for (int n = 0; n < 8; ++n)
#pragma unroll
            for (int i = 0; i < 4; ++i) S[n][i] = 0.f;

#pragma unroll
        for (int s = 0; s < 4; ++s) {
#pragma unroll
            for (int n = 0; n < 8; ++n) {
                int key = n * 8 + gr;
                int sw  = fsw(key);
                int w0  = tc + 8 * s, w1 = w0 + 4;
                uint32_t kb0 = pool[key * 32 + (w0 ^ sw)];
                uint32_t kb1 = pool[key * 32 + (w1 ^ sw)];
                uint32_t kc0 = pool[2048 + key * 32 + (w0 ^ sw)];
                uint32_t kc1 = pool[2048 + key * 32 + (w1 ^ sw)];
                mma16816(S[n], qh[s][0], qh[s][1], qh[s][2], qh[s][3], kb0, kb1);
                mma16816(S[n], qh[s][0], qh[s][1], qh[s][2], qh[s][3], kc0, kc1);
                mma16816(S[n], ql[s][0], ql[s][1], ql[s][2], ql[s][3], kb0, kb1);
            }
        }

        const bool domask = (j >= 2 * qt);
#pragma unroll
        for (int n = 0; n < 8; ++n) {
            int col = kv0 + 8 * n + 2 * tc;
            S[n][0] = fmaf(S[n][0], 0.125f, bb0r[n].x);
            S[n][1] = fmaf(S[n][1], 0.125f, bb0r[n].y);
            S[n][2] = fmaf(S[n][2], 0.125f, bb1r[n].x);
            S[n][3] = fmaf(S[n][3], 0.125f, bb1r[n].y);
            if (domask) {
                if (col     > row_g0) S[n][0] = -1e30f;
                if (col + 1 > row_g0) S[n][1] = -1e30f;
                if (col     > row_g1) S[n][2] = -1e30f;
                if (col + 1 > row_g1) S[n][3] = -1e30f;
            }
        }

        float t0 = -1e30f, t1 = -1e30f;
#pragma unroll
        for (int n = 0; n < 8; ++n) {
            t0 = fmaxf(t0, fmaxf(S[n][0], S[n][1]));
            t1 = fmaxf(t1, fmaxf(S[n][2], S[n][3]));
        }
        t0 = fmaxf(t0, __shfl_xor_sync(0xffffffffu, t0, 1));
        t0 = fmaxf(t0, __shfl_xor_sync(0xffffffffu, t0, 2));
        t1 = fmaxf(t1, __shfl_xor_sync(0xffffffffu, t1, 1));
        t1 = fmaxf(t1, __shfl_xor_sync(0xffffffffu, t1, 2));
        float mn0 = fmaxf(m0, t0), mn1 = fmaxf(m1, t1);
        float c0 = __expf(m0 - mn0), c1 = __expf(m1 - mn1);
        m0 = mn0; m1 = mn1;
        float ls0 = 0.f, ls1 = 0.f;
#pragma unroll
        for (int n = 0; n < 8; ++n) {
            S[n][0] = __expf(S[n][0] - m0); ls0 += S[n][0];
            S[n][1] = __expf(S[n][1] - m0); ls0 += S[n][1];
            S[n][2] = __expf(S[n][2] - m1); ls1 += S[n][2];
            S[n][3] = __expf(S[n][3] - m1); ls1 += S[n][3];
        }
        l0 = l0 * c0 + ls0;
        l1 = l1 * c1 + ls1;
#pragma unroll
        for (int n = 0; n < 8; ++n) {
            O[n][0] *= c0; O[n][1] *= c0;
            O[n][2] *= c1; O[n][3] *= c1;
        }

#pragma unroll
        for (int s = 0; s < 4; ++s) {
            uint32_t ph0, ph1, ph2, ph3, pl0, pl1, pl2, pl3;
            split2(S[2 * s][0],     S[2 * s][1],     ph0, pl0);
            split2(S[2 * s][2],     S[2 * s][3],     ph1, pl1);
            split2(S[2 * s + 1][0], S[2 * s + 1][1], ph2, pl2);
            split2(S[2 * s + 1][2], S[2 * s + 1][3], ph3, pl3);
#pragma unroll
            for (int n = 0; n < 8; ++n) {
                int d  = n * 8 + gr;
                int sw = fsw(d);
                int w0 = tc + 8 * s, w1 = w0 + 4;
                uint32_t vh0 = pool[4096 + d * 32 + (w0 ^ sw)];
                uint32_t vh1 = pool[4096 + d * 32 + (w1 ^ sw)];
                uint32_t vl0 = pool[6144 + d * 32 + (w0 ^ sw)];
                uint32_t vl1 = pool[6144 + d * 32 + (w1 ^ sw)];
                mma16816(O[n], ph0, ph1, ph2, ph3, vh0, vh1);
                mma16816(O[n], ph0, ph1, ph2, ph3, vl0, vl1);
                mma16816(O[n], pl0, pl1, pl2, pl3, vh0, vh1);
            }
        }
        __syncthreads();
    }

    // ---- finalize: O / l -> packed bf16 hi/lo y ----
    l0 += __shfl_xor_sync(0xffffffffu, l0, 1);
    l0 += __shfl_xor_sync(0xffffffffu, l0, 2);
    l1 += __shfl_xor_sync(0xffffffffu, l1, 1);
    l1 += __shfl_xor_sync(0xffffffffu, l1, 2);
    float inv0 = 1.f / l0, inv1 = 1.f / l1;

    const int b = bh / HN, h = bh % HN;
    const size_t base0 = (size_t)(b * TN + row_g0) * (DIMN / 2) + h * 32;
    const size_t base1 = (size_t)(b * TN + row_g1) * (DIMN / 2) + h * 32;
#pragma unroll
    for (int n = 0; n < 8; ++n) {
        int w = 4 * n + tc;
        uint32_t hp, lp;
        split2(O[n][0] * inv0, O[n][1] * inv0, hp, lp);
        g_yh[base0 + w] = hp;  g_yl[base0 + w] = lp;
        split2(O[n][2] * inv1, O[n][3] * inv1, hp, lp);
        g_yh[base1 + w] = hp;  g_yl[base1 + w] = lp;
    }
}

// ---------------------------------------------------------------------------
// Projection GEMM, pre-split bf16 inputs, cp.async double-buffered.
// out = y (4096x768) @ W (768x768).
// Block: 256 threads (8 warps = 4M x 2N), tile 128x128, K-chunk 64, 12 stages.
// smem: 2 buffers x 64KB: [Ah 16KB][Al 16KB][Bh 16KB][Bl 16KB]
// Layout per tile: row = 128 B (32 words = 64 bf16), chunk-swizzle c^=(r&7).
// ---------------------------------------------------------------------------
#define PROJ_SMEM (131072)
#define NSTAGE 12

__global__ __launch_bounds__(256) void proj_mma_kernel(float* __restrict__ out)
{
    extern __shared__ uint32_t pp[];

    const int tid  = threadIdx.x;
    const int wid  = tid >> 5;
    const int lane = tid & 31;
    const int gr   = lane >> 2;
    const int tc   = lane & 3;
    const int l8   = lane & 7;
    const int rsel = (lane & 16) ? 8 : 0;
    const int cpar = (lane >> 3) & 1;
    const int m_blk = blockIdx.y * 128;
    const int n_blk = blockIdx.x * 128;
    const int wm = (wid >> 1) * 32;
    const int wn = (wid & 1) * 64;

    const uint32_t sb = smem_u32(pp);

    // cp.async staging for stage st into buffer buf (16 chunks per thread)
    auto issue = [&](int st, int buf) {
        const uint32_t bb = sb + (uint32_t)buf * 65536;
        const uint32_t* asrcH = g_yh + (size_t)m_blk * (DIMN / 2) + st * 32;
        const uint32_t* asrcL = g_yl + (size_t)m_blk * (DIMN / 2) + st * 32;
        const uint32_t* bsrcH = g_wth + (size_t)n_blk * (DIMN / 2) + st * 32;
        const uint32_t* bsrcL = g_wtl + (size_t)n_blk * (DIMN / 2) + st * 32;
#pragma unroll
        for (int i = 0; i < 4; ++i) {
            int idx = tid + i * 256;           // 1024 chunks: r=idx>>3, c=idx&7
            int r = idx >> 3, c = idx & 7;
            uint32_t dof = (uint32_t)(r * 128 + ((c ^ (r & 7)) << 4));
            const uint32_t* ah = asrcH + (size_t)r * (DIMN / 2) + c * 4;
            const uint32_t* al = asrcL + (size_t)r * (DIMN / 2) + c * 4;
            const uint32_t* bh = bsrcH + (size_t)r * (DIMN / 2) + c * 4;
            const uint32_t* bl = bsrcL + (size_t)r * (DIMN / 2) + c * 4;
            cpasync16(bb + dof, ah);
            cpasync16(bb + 16384 + dof, al);
            cpasync16(bb + 32768 + dof, bh);
            cpasync16(bb + 49152 + dof, bl);
        }
        CP_COMMIT();
    };

    issue(0, 0);
    issue(1, 1);

    float C[2][8][4];
#pragma unroll
    for (int mi = 0; mi < 2; ++mi)
#pragma unroll
        for (int n = 0; n < 8; ++n)
#pragma unroll
            for (int i = 0; i < 4; ++i) C[mi][n][i] = 0.f;

    for (int j = 0; j < NSTAGE; ++j) {
        if (j < NSTAGE - 1) { CP_WAIT1(); } else { CP_WAIT0(); }
        __syncthreads();

        const uint32_t bb = sb + (uint32_t)(j & 1) * 65536;
        const uint32_t arow = bb + (uint32_t)(wm + (lane & 15)) * 128;
        const uint32_t brow = bb + 32768 + (uint32_t)(wn + rsel + l8) * 128;

#pragma unroll
        for (int s = 0; s < 4; ++s) {
            uint32_t ah[2][4], al[2][4];
            uint32_t asw = (uint32_t)(((2 * s + (lane >> 4)) ^ l8) << 4);
#pragma unroll
            for (int mi = 0; mi < 2; ++mi) {
                uint32_t a = arow + (uint32_t)(16 * mi) * 128 + asw;
                ldsm4(ah[mi], a);
                ldsm4(al[mi], a + 16384);
            }
            uint32_t bsw = (uint32_t)(((2 * s + cpar) ^ l8) << 4);
#pragma unroll
            for (int np = 0; np < 4; ++np) {
                uint32_t bh4[4], bl4[4];
                uint32_t a = brow + (uint32_t)np * 2048 + bsw;
                ldsm4(bh4, a);
                ldsm4(bl4, a + 16384);
#pragma unroll
                for (int mi = 0; mi < 2; ++mi) {
                    float* C0 = C[mi][2 * np];
                    float* C1 = C[mi][2 * np + 1];
                    mma16816(C0, ah[mi][0], ah[mi][1], ah[mi][2], ah[mi][3], bh4[0], bh4[1]);
                    mma16816(C0, ah[mi][0], ah[mi][1], ah[mi][2], ah[mi][3], bl4[0], bl4[1]);
                    mma16816(C0, al[mi][0], al[mi][1], al[mi][2], al[mi][3], bh4[0], bh4[1]);
                    mma16816(C1, ah[mi][0], ah[mi][1], ah[mi][2], ah[mi][3], bh4[2], bh4[3]);
                    mma16816(C1, ah[mi][0], ah[mi][1], ah[mi][2], ah[mi][3], bl4[2], bl4[3]);
                    mma16816(C1, al[mi][0], al[mi][1], al[mi][2], al[mi][3], bh4[2], bh4[3]);
                }
            }
        }
        __syncthreads();
        if (j + 2 < NSTAGE) issue(j + 2, j & 1);
    }

#pragma unroll
    for (int mi = 0; mi < 2; ++mi) {
        int row0 = m_blk + wm + 16 * mi + gr;
        int row1 = row0 + 8;
#pragma unroll
        for (int n = 0; n < 8; ++n) {
            int col = n_blk + wn + 8 * n + 2 * tc;
            float2 w0, w1;
            w0.x = C[mi][n][0]; w0.y = C[mi][n][1];
            w1.x = C[mi][n][2]; w1.y = C[mi][n][3];
            *reinterpret_cast<float2*>(out + (size_t)row0 * DIMN + col) = w0;
            *reinterpret_cast<float2*>(out + (size_t)row1 * DIMN + col) = w1;
        }
    }
}

extern "C" void kernel_launch(void* const* d_in, const int* in_sizes, int n_in,
                              void* d_out, int out_size)
{
    (void)in_sizes; (void)n_in; (void)out_size;
    const float* q    = (const float*)d_in[0];
    const float* k    = (const float*)d_in[1];
    const float* v    = (const float*)d_in[2];
    const float* bias = (const float*)d_in[3];
    const float* W    = (const float*)d_in[4];
    float* out = (float*)d_out;

    prep_w_kernel<<<dim3(DIMN / 64, DIMN / 64), 256>>>(W);

    cudaFuncSetAttribute(attn_mma_kernel,
                         cudaFuncAttributeMaxDynamicSharedMemorySize, ATTN_SMEM);
    attn_mma_kernel<<<dim3(TN / QTIL, BSZ * HN), 256, ATTN_SMEM>>>(q, k, v, bias);

    cudaFuncSetAttribute(proj_mma_kernel,
                         cudaFuncAttributeMaxDynamicSharedMemorySize, PROJ_SMEM);
    proj_mma_kernel<<<dim3(DIMN / 128, (BSZ * TN) / 128), 256, PROJ_SMEM>>>(out);
}